// round 2
// baseline (speedup 1.0000x reference)
#include <cuda_runtime.h>
#include <cuda_bf16.h>

#define TILE_W 128
#define TILE_H 128
#define WIN    11
#define HALO   5

// One CTA = 128x128 output tile of one image. 128 threads, thread t = output
// column (colBase + t). Sliding vertical window over 138 input rows:
//   - stage img/ref row (+-5 halo) into smem
//   - per-thread 11-tap horizontal sums of (x, y, x^2, y^2, x*y)
//   - 11-deep smem ring buffer for vertical running sums
//   - emit SSIM for output row once 11 rows accumulated
__global__ __launch_bounds__(TILE_W) void ssim_kernel(
    const float* __restrict__ img,
    const float* __restrict__ ref,
    const float* __restrict__ drange,
    float* __restrict__ out,
    int H, int W)
{
    __shared__ float rowA[TILE_W + 2 * HALO + 2];   // +2 pad
    __shared__ float rowB[TILE_W + 2 * HALO + 2];
    __shared__ float ring[5][WIN][TILE_W];          // 5 * 11 * 128 * 4B = 27.5 KB

    const int tid     = threadIdx.x;
    const int colBase = blockIdx.x * TILE_W;
    const int rowBase = blockIdx.y * TILE_H;
    const int b       = blockIdx.z;

    const float dr = drange[b];
    const float C1 = (0.01f * dr) * (0.01f * dr);
    const float C2 = (0.03f * dr) * (0.03f * dr);

    const size_t base = (size_t)b * H * W;
    const float* __restrict__ imgB = img + base;
    const float* __restrict__ refB = ref + base;
    float* __restrict__ outB = out + base;

    float acc0 = 0.f, acc1 = 0.f, acc2 = 0.f, acc3 = 0.f, acc4 = 0.f;

    for (int i = 0; i < TILE_H + 2 * HALO; ++i) {
        const int gy = rowBase - HALO + i;

        // ---- stage one input row (with horizontal halo), zero-padded ----
        for (int j = tid; j < TILE_W + 2 * HALO; j += TILE_W) {
            const int gx = colBase - HALO + j;
            float a = 0.f, c = 0.f;
            if ((unsigned)gy < (unsigned)H && (unsigned)gx < (unsigned)W) {
                const size_t idx = (size_t)gy * W + gx;
                a = imgB[idx];
                c = refB[idx];
            }
            rowA[j] = a;
            rowB[j] = c;
        }
        __syncthreads();

        // ---- horizontal 11-tap sums (stride-1 smem reads: conflict-free) ----
        float sx = 0.f, sy = 0.f, sxx = 0.f, syy = 0.f, sxy = 0.f;
        #pragma unroll
        for (int k = 0; k < WIN; ++k) {
            const float a = rowA[tid + k];
            const float c = rowB[tid + k];
            sx += a;
            sy += c;
            sxx = fmaf(a, a, sxx);
            syy = fmaf(c, c, syy);
            sxy = fmaf(a, c, sxy);
        }

        // ---- vertical running sums via ring buffer ----
        const int slot = i % WIN;
        if (i >= WIN) {
            acc0 -= ring[0][slot][tid];
            acc1 -= ring[1][slot][tid];
            acc2 -= ring[2][slot][tid];
            acc3 -= ring[3][slot][tid];
            acc4 -= ring[4][slot][tid];
        }
        acc0 += sx;  acc1 += sy;  acc2 += sxx;  acc3 += syy;  acc4 += sxy;
        ring[0][slot][tid] = sx;
        ring[1][slot][tid] = sy;
        ring[2][slot][tid] = sxx;
        ring[3][slot][tid] = syy;
        ring[4][slot][tid] = sxy;

        // ---- emit output row (center of the 11-row window) ----
        if (i >= 2 * HALO) {
            const int oy = rowBase + i - 2 * HALO;
            const float inv121 = 1.0f / 121.0f;
            const float covn   = 121.0f / 120.0f;

            const float ux  = acc0 * inv121;
            const float uy  = acc1 * inv121;
            const float uxx = acc2 * inv121;
            const float uyy = acc3 * inv121;
            const float uxy = acc4 * inv121;

            const float vx  = covn * (uxx - ux * ux);
            const float vy  = covn * (uyy - uy * uy);
            const float vxy = covn * (uxy - ux * uy);

            const float A1 = 2.f * ux * uy + C1;
            const float A2 = 2.f * vxy + C2;
            const float B1 = ux * ux + uy * uy + C1;
            const float B2 = vx + vy + C2;

            const float S = __fdividef(A1 * A2, B1 * B2);
            outB[(size_t)oy * W + colBase + tid] = S;
        }
        __syncthreads();   // protect staging buffers before next row overwrite
    }
}

extern "C" void kernel_launch(void* const* d_in, const int* in_sizes, int n_in,
                              void* d_out, int out_size) {
    const float* img = (const float*)d_in[0];
    const float* ref = (const float*)d_in[1];
    const float* dr  = (const float*)d_in[2];
    float* out = (float*)d_out;

    const int B = in_sizes[2];      // data_range has B elements
    const int H = 512, W = 512;     // fixed problem shape (B,1,512,512)

    dim3 grid(W / TILE_W, H / TILE_H, B);
    ssim_kernel<<<grid, TILE_W>>>(img, ref, dr, out, H, W);
}

// round 4
// speedup vs baseline: 1.8858x; 1.8858x over previous
#include <cuda_runtime.h>
#include <cuda_bf16.h>

#define WIN    11
#define HALO   5
#define TILE_H 64
#define NT     128       // threads per CTA; each owns 4 consecutive columns
#define IMW    512
#define IMH    512

// Dynamic smem ring: [WIN][5 quantities][NT] of float4 (4 cols per thread)
// = 11 * 5 * 128 * 16 B = 112,640 B  -> 2 CTAs/SM on sm_103a.
#define RING_BYTES (WIN * 5 * NT * 16)

__global__ __launch_bounds__(NT) void ssim_kernel(
    const float* __restrict__ img,
    const float* __restrict__ ref,
    const float* __restrict__ drange,
    float* __restrict__ out)
{
    extern __shared__ float4 ring[];      // [WIN][5][NT]

    const int t       = threadIdx.x;
    const int b       = blockIdx.x;       // batch image
    const int rowBase = blockIdx.y * TILE_H;

    const float dr   = drange[b];
    // Work on raw window sums S* (un-normalized). The 1/121 factors cancel in
    // the final ratio, so fold 121^2 into C1/C2 instead:
    const float c1    = (0.01f * dr) * (0.01f * dr) * 14641.0f;
    const float c2    = (0.03f * dr) * (0.03f * dr) * 14641.0f;
    const float covn  = 121.0f / 120.0f;
    const float covn2 = 2.0f * covn;

    const size_t base = (size_t)b * IMW * IMH;
    const float* ra = img + base + (long)(rowBase - HALO) * IMW;
    const float* rb = ref + base + (long)(rowBase - HALO) * IMW;
    float*       ro = out + base + (size_t)rowBase * IMW + 4 * t;

    // 5 aligned float4 blocks per image cover cols [4t-8, 4t+11] ⊇ taps [4t-5, 4t+8].
    const int col0 = 4 * t - 8;
    bool bval[5];
    #pragma unroll
    for (int k = 0; k < 5; ++k) bval[k] = (unsigned)(col0 + 4 * k) < IMW;

    // Vertical accumulators: 5 quantities x 4 columns (registers).
    float ax[4], ay[4], axx[4], ayy[4], axy[4];
    #pragma unroll
    for (int c = 0; c < 4; ++c) { ax[c]=0.f; ay[c]=0.f; axx[c]=0.f; ayy[c]=0.f; axy[c]=0.f; }

    float4* rp = ring + t;               // slot 0, quantity stride = NT float4s

    for (int i = 0; i < TILE_H + 2 * HALO; ++i) {
        const int gy = rowBase - HALO + i;

        // ---- horizontal sums for this input row, 4 columns via sliding ----
        float sxa[4], sya[4], sxxa[4], syya[4], sxya[4];
        if ((unsigned)gy < (unsigned)IMH) {
            float af[20], bf[20];
            #pragma unroll
            for (int k = 0; k < 5; ++k) {
                float4 va = make_float4(0.f, 0.f, 0.f, 0.f);
                float4 vb = va;
                if (bval[k]) {
                    va = *(const float4*)(ra + col0 + 4 * k);
                    vb = *(const float4*)(rb + col0 + 4 * k);
                }
                af[4*k+0]=va.x; af[4*k+1]=va.y; af[4*k+2]=va.z; af[4*k+3]=va.w;
                bf[4*k+0]=vb.x; bf[4*k+1]=vb.y; bf[4*k+2]=vb.z; bf[4*k+3]=vb.w;
            }

            // initial 11-tap sums for column 4t (taps af[3..13])
            float sx=0.f, sy=0.f, sxx=0.f, syy=0.f, sxy=0.f;
            #pragma unroll
            for (int j = 3; j < 14; ++j) {
                const float a = af[j], bbv = bf[j];
                sx += a; sy += bbv;
                sxx = fmaf(a, a, sxx);
                syy = fmaf(bbv, bbv, syy);
                sxy = fmaf(a, bbv, sxy);
            }
            sxa[0]=sx; sya[0]=sy; sxxa[0]=sxx; syya[0]=syy; sxya[0]=sxy;

            // slide to columns 4t+1..4t+3
            #pragma unroll
            for (int s = 1; s < 4; ++s) {
                const float ai = af[13+s], ao = af[2+s];
                const float bi = bf[13+s], bo = bf[2+s];
                sx += ai - ao;
                sy += bi - bo;
                sxx = fmaf(ai, ai, sxx);  sxx = fmaf(-ao, ao, sxx);
                syy = fmaf(bi, bi, syy);  syy = fmaf(-bo, bo, syy);
                sxy = fmaf(ai, bi, sxy);  sxy = fmaf(-ao, bo, sxy);
                sxa[s]=sx; sya[s]=sy; sxxa[s]=sxx; syya[s]=syy; sxya[s]=sxy;
            }
        } else {
            #pragma unroll
            for (int c = 0; c < 4; ++c) { sxa[c]=0.f; sya[c]=0.f; sxxa[c]=0.f; syya[c]=0.f; sxya[c]=0.f; }
        }
        ra += IMW; rb += IMW;

        // ---- vertical sliding window via per-thread-private smem ring ----
        if (i >= WIN) {
            float4 o;
            o = rp[0*NT]; ax[0]-=o.x;  ax[1]-=o.y;  ax[2]-=o.z;  ax[3]-=o.w;
            o = rp[1*NT]; ay[0]-=o.x;  ay[1]-=o.y;  ay[2]-=o.z;  ay[3]-=o.w;
            o = rp[2*NT]; axx[0]-=o.x; axx[1]-=o.y; axx[2]-=o.z; axx[3]-=o.w;
            o = rp[3*NT]; ayy[0]-=o.x; ayy[1]-=o.y; ayy[2]-=o.z; ayy[3]-=o.w;
            o = rp[4*NT]; axy[0]-=o.x; axy[1]-=o.y; axy[2]-=o.z; axy[3]-=o.w;
        }
        #pragma unroll
        for (int c = 0; c < 4; ++c) {
            ax[c]+=sxa[c]; ay[c]+=sya[c]; axx[c]+=sxxa[c]; ayy[c]+=syya[c]; axy[c]+=sxya[c];
        }
        rp[0*NT] = make_float4(sxa[0],  sxa[1],  sxa[2],  sxa[3]);
        rp[1*NT] = make_float4(sya[0],  sya[1],  sya[2],  sya[3]);
        rp[2*NT] = make_float4(sxxa[0], sxxa[1], sxxa[2], sxxa[3]);
        rp[3*NT] = make_float4(syya[0], syya[1], syya[2], syya[3]);
        rp[4*NT] = make_float4(sxya[0], sxya[1], sxya[2], sxya[3]);
        rp += 5 * NT;
        if (rp >= ring + WIN * 5 * NT) rp = ring + t;

        // ---- emit output row (window of 11 input rows complete) ----
        if (i >= 2 * HALO) {
            float rr[4];
            #pragma unroll
            for (int c = 0; c < 4; ++c) {
                const float Sx = ax[c],  Sy = ay[c];
                const float Sxx = axx[c], Syy = ayy[c], Sxy = axy[c];
                const float p  = Sx * Sy;
                const float xx = Sx * Sx;
                const float yy = Sy * Sy;
                const float A1 = fmaf(2.0f, p, c1);
                const float B1 = xx + yy + c1;
                const float A2 = fmaf(covn2, fmaf(121.0f, Sxy, -p), c2);
                const float vx = fmaf(121.0f, Sxx, -xx);
                const float vy = fmaf(121.0f, Syy, -yy);
                const float B2 = fmaf(covn, vx + vy, c2);
                rr[c] = __fdividef(A1 * A2, B1 * B2);
            }
            *(float4*)ro = make_float4(rr[0], rr[1], rr[2], rr[3]);
            ro += IMW;
        }
    }
}

extern "C" void kernel_launch(void* const* d_in, const int* in_sizes, int n_in,
                              void* d_out, int out_size) {
    const float* img = (const float*)d_in[0];
    const float* ref = (const float*)d_in[1];
    const float* dr  = (const float*)d_in[2];
    float* out = (float*)d_out;

    const int B = in_sizes[2];   // 64

    cudaFuncSetAttribute(ssim_kernel,
                         cudaFuncAttributeMaxDynamicSharedMemorySize, RING_BYTES);

    dim3 grid(B, IMH / TILE_H, 1);   // (64, 8) = 512 CTAs, 74 input rows each
    ssim_kernel<<<grid, NT, RING_BYTES>>>(img, ref, dr, out);
}

// round 10
// speedup vs baseline: 3.1169x; 1.6528x over previous
#include <cuda_runtime.h>
#include <cuda_bf16.h>

#define WIN    11
#define HALO   5
#define TILE_H 32
#define NT     128       // threads per CTA; thread t owns columns 4t..4t+3
#define IMW    512
#define IMH    512

// Horizontal 11-tap sums of (x, y, x^2, y^2, xy) for 4 consecutive columns.
struct HS { float sx[4], sy[4], sxx[4], syy[4], sxy[4]; };

// Row pointers point at column 0 of the row; col0 = 4t-8 (may be <0 / >W-4).
// 5 aligned float4 blocks cover cols [4t-8, 4t+11] ⊇ taps [4t-5, 4t+8].
__device__ __forceinline__ HS hsums(const float* __restrict__ ra,
                                    const float* __restrict__ rb,
                                    int col0)
{
    float af[20], bf[20];
    #pragma unroll
    for (int k = 0; k < 5; ++k) {
        float4 va = make_float4(0.f, 0.f, 0.f, 0.f);
        float4 vb = va;
        if ((unsigned)(col0 + 4 * k) < IMW) {
            va = *(const float4*)(ra + col0 + 4 * k);
            vb = *(const float4*)(rb + col0 + 4 * k);
        }
        af[4*k+0]=va.x; af[4*k+1]=va.y; af[4*k+2]=va.z; af[4*k+3]=va.w;
        bf[4*k+0]=vb.x; bf[4*k+1]=vb.y; bf[4*k+2]=vb.z; bf[4*k+3]=vb.w;
    }

    HS h;
    // initial 11-tap sums for column 4t (taps af[3..13])
    float sx=0.f, sy=0.f, sxx=0.f, syy=0.f, sxy=0.f;
    #pragma unroll
    for (int j = 3; j < 14; ++j) {
        const float a = af[j], c = bf[j];
        sx += a; sy += c;
        sxx = fmaf(a, a, sxx);
        syy = fmaf(c, c, syy);
        sxy = fmaf(a, c, sxy);
    }
    h.sx[0]=sx; h.sy[0]=sy; h.sxx[0]=sxx; h.syy[0]=syy; h.sxy[0]=sxy;

    // slide to columns 4t+1..4t+3
    #pragma unroll
    for (int s = 1; s < 4; ++s) {
        const float ai = af[13+s], ao = af[2+s];
        const float bi = bf[13+s], bo = bf[2+s];
        sx += ai - ao;
        sy += bi - bo;
        sxx = fmaf(ai, ai, sxx);  sxx = fmaf(-ao, ao, sxx);
        syy = fmaf(bi, bi, syy);  syy = fmaf(-bo, bo, syy);
        sxy = fmaf(ai, bi, sxy);  sxy = fmaf(-ao, bo, sxy);
        h.sx[s]=sx; h.sy[s]=sy; h.sxx[s]=sxx; h.syy[s]=syy; h.sxy[s]=sxy;
    }
    return h;
}

// No smem, no barriers. Vertical sliding window: add the incoming row's
// horizontal sums; subtract the leaving row's by RECOMPUTING them from a
// re-read of that row (11 rows back -> L1/L2 resident). Occupancy is then
// register-limited (~5 CTAs/SM) instead of smem-limited (2 CTAs/SM).
__global__ __launch_bounds__(NT) void ssim_kernel(
    const float* __restrict__ img,
    const float* __restrict__ ref,
    const float* __restrict__ drange,
    float* __restrict__ out)
{
    const int t       = threadIdx.x;
    const int b       = blockIdx.x;
    const int rowBase = blockIdx.y * TILE_H;
    const int col0    = 4 * t - 8;

    const float dr    = drange[b];
    // Raw (un-normalized) window sums; fold 121^2 into the constants.
    const float c1    = (0.01f * dr) * (0.01f * dr) * 14641.0f;
    const float c2    = (0.03f * dr) * (0.03f * dr) * 14641.0f;
    const float covn  = 121.0f / 120.0f;
    const float covn2 = 2.0f * covn;

    const size_t base = (size_t)b * IMW * IMH;
    const float* pa = img + base + (long)(rowBase - HALO) * IMW;   // incoming row
    const float* pb = ref + base + (long)(rowBase - HALO) * IMW;
    float*       ro = out + base + (size_t)rowBase * IMW + 4 * t;

    float ax[4], ay[4], axx[4], ayy[4], axy[4];
    #pragma unroll
    for (int c = 0; c < 4; ++c) { ax[c]=0.f; ay[c]=0.f; axx[c]=0.f; ayy[c]=0.f; axy[c]=0.f; }

    for (int i = 0; i < TILE_H + 2 * HALO; ++i) {
        const int gy = rowBase - HALO + i;

        // ---- add incoming row ----
        if ((unsigned)gy < (unsigned)IMH) {
            HS h = hsums(pa, pb, col0);
            #pragma unroll
            for (int c = 0; c < 4; ++c) {
                ax[c]  += h.sx[c];  ay[c]  += h.sy[c];
                axx[c] += h.sxx[c]; ayy[c] += h.syy[c]; axy[c] += h.sxy[c];
            }
        }

        // ---- subtract leaving row (added 11 iterations ago), recomputed ----
        const int gys = gy - WIN;
        if (i >= WIN && (unsigned)gys < (unsigned)IMH) {
            HS h = hsums(pa - WIN * IMW, pb - WIN * IMW, col0);
            #pragma unroll
            for (int c = 0; c < 4; ++c) {
                ax[c]  -= h.sx[c];  ay[c]  -= h.sy[c];
                axx[c] -= h.sxx[c]; ayy[c] -= h.syy[c]; axy[c] -= h.sxy[c];
            }
        }
        pa += IMW; pb += IMW;

        // ---- emit output row once 11-row window is complete ----
        if (i >= 2 * HALO) {
            float rr[4];
            #pragma unroll
            for (int c = 0; c < 4; ++c) {
                const float Sx = ax[c],  Sy = ay[c];
                const float Sxx = axx[c], Syy = ayy[c], Sxy = axy[c];
                const float p  = Sx * Sy;
                const float xx = Sx * Sx;
                const float yy = Sy * Sy;
                const float A1 = fmaf(2.0f, p, c1);
                const float B1 = xx + yy + c1;
                const float A2 = fmaf(covn2, fmaf(121.0f, Sxy, -p), c2);
                const float vx = fmaf(121.0f, Sxx, -xx);
                const float vy = fmaf(121.0f, Syy, -yy);
                const float B2 = fmaf(covn, vx + vy, c2);
                rr[c] = __fdividef(A1 * A2, B1 * B2);
            }
            *(float4*)ro = make_float4(rr[0], rr[1], rr[2], rr[3]);
            ro += IMW;
        }
    }
}

extern "C" void kernel_launch(void* const* d_in, const int* in_sizes, int n_in,
                              void* d_out, int out_size) {
    const float* img = (const float*)d_in[0];
    const float* ref = (const float*)d_in[1];
    const float* dr  = (const float*)d_in[2];
    float* out = (float*)d_out;

    const int B = in_sizes[2];   // 64

    dim3 grid(B, IMH / TILE_H, 1);   // (64, 16) = 1024 CTAs, 42 input rows each
    ssim_kernel<<<grid, NT>>>(img, ref, dr, out);
}